// round 7
// baseline (speedup 1.0000x reference)
#include <cuda_runtime.h>
#include <math.h>
#include <stdint.h>
#include <mma.h>

using namespace nvcuda;

#define Bdim 64
#define Tdim 512
#define Idim 256
#define Hdim 512
#define BH   (Bdim*Hdim)   // 32768

// Scratch (device globals: no allocations allowed)
__device__ float g_xw[(size_t)Tdim*Bdim*Hdim];  // 64 MB, [T,B,H] rows m=t*64+b
__device__ float g_h [(size_t)Tdim*Bdim*Hdim];  // 64 MB, [T,B,H]
__device__ int   g_flag[2][8][32];              // [layer][bblk][jblk] step flags

__global__ void zero_flags_k() {
    int i = blockIdx.x * blockDim.x + threadIdx.x;
    if (i < 2 * 8 * 32) ((int*)g_flag)[i] = 0;
}

__device__ __forceinline__ void st_release_gpu(int* p, int v) {
    asm volatile("st.release.gpu.u32 [%0], %1;" :: "l"(p), "r"(v) : "memory");
}
__device__ __forceinline__ int ld_acquire_gpu(const int* p) {
    int v;
    asm volatile("ld.acquire.gpu.u32 %0, [%1];" : "=r"(v) : "l"(p) : "memory");
    return v;
}

// ---------------------------------------------------------------------------
// 3xTF32 tensor-core projection GEMM (near-fp32 accuracy).
// g_xw[m][n] = sum_k A[m][k] * W[n][k] + b1[n] + b2[n]
// v = hi + lo (hi = tf32-rounded); C += hi*hi + hi*lo + lo*hi.
// CTA tile: M=128, N=64, K chunked by 32. 8 warps, each 32x32 (2x2 wmma 16x16x8).
// FIRST: A = x with layout [B,T,I]  (row m=t*64+b -> offset (b*T+t)*KD)
// else : A = g_h with row-major rows m (offset m*KD)
// ---------------------------------------------------------------------------
#define LDA 40                       // 32 + 8 skew
#define A_FL (128 * LDA)
#define B_FL (64 * LDA)
#define TOT_FL (2 * (A_FL + B_FL))   // 15360 floats = 61440 B
#define LDC 72                       // 64 + 8 skew

template<int KD, bool FIRST>
__global__ __launch_bounds__(256, 2) void proj_tc(
    const float* __restrict__ xin, const float* __restrict__ W,
    const float* __restrict__ b1,  const float* __restrict__ b2)
{
    extern __shared__ float s[];     // [A_hi | A_lo | B_hi | B_lo]; reused as C
    float* As_hi = s;
    float* As_lo = s + A_FL;
    float* Bs_hi = s + 2 * A_FL;
    float* Bs_lo = s + 2 * A_FL + B_FL;
    __shared__ float biasS[64];

    const float* __restrict__ A = FIRST ? xin : g_h;
    const int tid = threadIdx.x;
    const int wid = tid >> 5;
    const int n0 = blockIdx.x * 64;
    const int m0 = blockIdx.y * 128;
    const int wm = wid & 3;
    const int wn = wid >> 2;

    if (tid < 64) biasS[tid] = b1[n0 + tid] + b2[n0 + tid];

    int a_row[4], a_col[4];
    #pragma unroll
    for (int i = 0; i < 4; i++) {
        int idx = tid + i * 256;
        a_row[i] = idx >> 3;
        a_col[i] = (idx & 7) * 4;
    }
    int b_row[2], b_col[2];
    #pragma unroll
    for (int i = 0; i < 2; i++) {
        int idx = tid + i * 256;
        b_row[i] = idx >> 3;
        b_col[i] = (idx & 7) * 4;
    }

    size_t a_off[4];
    #pragma unroll
    for (int i = 0; i < 4; i++) {
        int m = m0 + a_row[i];
        a_off[i] = FIRST ? ((size_t)(m & 63) * Tdim + (m >> 6)) * KD
                         : (size_t)m * KD;
    }
    size_t b_off[2];
    #pragma unroll
    for (int i = 0; i < 2; i++)
        b_off[i] = (size_t)(n0 + b_row[i]) * KD;

    wmma::fragment<wmma::accumulator, 16, 16, 8, float> cf[2][2];
    #pragma unroll
    for (int i = 0; i < 2; i++)
        #pragma unroll
        for (int j = 0; j < 2; j++)
            wmma::fill_fragment(cf[i][j], 0.0f);

    float4 pa[4], pb[2];
    #pragma unroll
    for (int i = 0; i < 4; i++)
        pa[i] = *reinterpret_cast<const float4*>(A + a_off[i] + a_col[i]);
    #pragma unroll
    for (int i = 0; i < 2; i++)
        pb[i] = *reinterpret_cast<const float4*>(W + b_off[i] + b_col[i]);

    const int KT = KD / 32;
    for (int kt = 0; kt < KT; ++kt) {
        #pragma unroll
        for (int i = 0; i < 4; i++) {
            int o = a_row[i] * LDA + a_col[i];
            float hx = wmma::__float_to_tf32(pa[i].x);
            float hy = wmma::__float_to_tf32(pa[i].y);
            float hz = wmma::__float_to_tf32(pa[i].z);
            float hw = wmma::__float_to_tf32(pa[i].w);
            As_hi[o+0] = hx; As_hi[o+1] = hy; As_hi[o+2] = hz; As_hi[o+3] = hw;
            As_lo[o+0] = pa[i].x - hx; As_lo[o+1] = pa[i].y - hy;
            As_lo[o+2] = pa[i].z - hz; As_lo[o+3] = pa[i].w - hw;
        }
        #pragma unroll
        for (int i = 0; i < 2; i++) {
            int o = b_row[i] * LDA + b_col[i];
            float hx = wmma::__float_to_tf32(pb[i].x);
            float hy = wmma::__float_to_tf32(pb[i].y);
            float hz = wmma::__float_to_tf32(pb[i].z);
            float hw = wmma::__float_to_tf32(pb[i].w);
            Bs_hi[o+0] = hx; Bs_hi[o+1] = hy; Bs_hi[o+2] = hz; Bs_hi[o+3] = hw;
            Bs_lo[o+0] = pb[i].x - hx; Bs_lo[o+1] = pb[i].y - hy;
            Bs_lo[o+2] = pb[i].z - hz; Bs_lo[o+3] = pb[i].w - hw;
        }
        __syncthreads();

        if (kt + 1 < KT) {
            int k0 = (kt + 1) * 32;
            #pragma unroll
            for (int i = 0; i < 4; i++)
                pa[i] = *reinterpret_cast<const float4*>(A + a_off[i] + k0 + a_col[i]);
            #pragma unroll
            for (int i = 0; i < 2; i++)
                pb[i] = *reinterpret_cast<const float4*>(W + b_off[i] + k0 + b_col[i]);
        }

        #pragma unroll
        for (int kk = 0; kk < 32; kk += 8) {
            wmma::fragment<wmma::matrix_a, 16, 16, 8, wmma::precision::tf32, wmma::row_major> ah[2], al[2];
            wmma::fragment<wmma::matrix_b, 16, 16, 8, wmma::precision::tf32, wmma::col_major> bh[2], bl[2];
            #pragma unroll
            for (int i = 0; i < 2; i++) {
                wmma::load_matrix_sync(ah[i], As_hi + (wm * 32 + i * 16) * LDA + kk, LDA);
                wmma::load_matrix_sync(al[i], As_lo + (wm * 32 + i * 16) * LDA + kk, LDA);
            }
            #pragma unroll
            for (int j = 0; j < 2; j++) {
                wmma::load_matrix_sync(bh[j], Bs_hi + (wn * 32 + j * 16) * LDA + kk, LDA);
                wmma::load_matrix_sync(bl[j], Bs_lo + (wn * 32 + j * 16) * LDA + kk, LDA);
            }
            #pragma unroll
            for (int i = 0; i < 2; i++)
                #pragma unroll
                for (int j = 0; j < 2; j++) {
                    wmma::mma_sync(cf[i][j], al[i], bh[j], cf[i][j]);
                    wmma::mma_sync(cf[i][j], ah[i], bl[j], cf[i][j]);
                    wmma::mma_sync(cf[i][j], ah[i], bh[j], cf[i][j]);
                }
        }
        __syncthreads();
    }

    #pragma unroll
    for (int i = 0; i < 2; i++)
        #pragma unroll
        for (int j = 0; j < 2; j++)
            wmma::store_matrix_sync(s + (wm * 32 + i * 16) * LDC + wn * 32 + j * 16,
                                    cf[i][j], LDC, wmma::mem_row_major);
    __syncthreads();

    #pragma unroll
    for (int i = 0; i < 8; i++) {
        int idx = tid + i * 256;
        int row = idx >> 4;
        int col = (idx & 15) * 4;
        float4 o;
        o.x = s[row * LDC + col + 0] + biasS[col + 0];
        o.y = s[row * LDC + col + 1] + biasS[col + 1];
        o.z = s[row * LDC + col + 2] + biasS[col + 2];
        o.w = s[row * LDC + col + 3] + biasS[col + 3];
        *reinterpret_cast<float4*>(&g_xw[(size_t)(m0 + row) * Hdim + n0 + col]) = o;
    }
}

// ---------------------------------------------------------------------------
// Recurrent scan: h[t] = relu(xw[t] + h[t-1] @ Whh^T), persistent kernel.
// Grid (16 j-blocks, 8 b-blocks) = 128 CTAs, 256 threads each.
// W slice in registers. Per-warp sync/load: warp w consumes k-chunk
// [w*64,(w+1)*64) produced by jblks {2w, 2w+1} only -- each warp polls its
// own two flags and immediately loads its own 2KB h slice, so early
// producers' data streams in while late producers are still polled.
// ---------------------------------------------------------------------------
__global__ __launch_bounds__(256) void rnn_scan(const float* __restrict__ Whh, int layer)
{
    __shared__ __align__(16) float hs[8 * 512];        // h_prev slice (8 batch rows)
    __shared__ __align__(16) float part[8 * 8 * 32];   // per-warp partials

    const int tid  = threadIdx.x;
    const int w    = tid >> 5;
    const int lane = tid & 31;
    const int jblk = blockIdx.x;   // 0..15
    const int bblk = blockIdx.y;   // 0..7
    const int j = jblk * 32 + lane;
    const int rowbase = bblk * 8;
    const int* flags = &g_flag[layer][bblk][0];
    int* myflag = &g_flag[layer][bblk][jblk];

    // Weight-stationary registers: Whh[j][w*64 .. w*64+63]
    float4 wv[16];
    const float4* Wr = reinterpret_cast<const float4*>(Whh + (size_t)j * Hdim + w * 64);
    #pragma unroll
    for (int i = 0; i < 16; i++) wv[i] = Wr[i];

    float4* hs4 = reinterpret_cast<float4*>(hs);

    const int b2 = tid >> 5, j2 = tid & 31;
    const size_t outbase = (size_t)(rowbase + b2) * Hdim + jblk * 32 + j2;

    // Per-warp h-load slots: warp w covers float4 cols [w*16, w*16+16) of each row
    int l_b[4], l_q[4];
    #pragma unroll
    for (int i = 0; i < 4; i++) {
        int idx = lane + i * 32;      // 0..127
        l_b[i] = idx >> 4;            // row 0..7
        l_q[i] = idx & 15;            // float4 col within warp chunk
    }

    for (int t = 0; t < Tdim; ++t) {
        // Prefetch xw for this thread's output slot (independent of h[t-1])
        const size_t off = (size_t)t * BH + outbase;
        float xv = __ldcg(&g_xw[off]);

        if (t > 0) {
            // Warp w waits only on its two producers (jblk 2w, 2w+1)
            for (;;) {
                int v = (lane < 2) ? ld_acquire_gpu(flags + 2 * w + lane) : 0x7fffffff;
                if (__all_sync(0xffffffffu, v >= t)) break;
            }
            const float4* src = reinterpret_cast<const float4*>(
                g_h + (size_t)(t - 1) * BH + (size_t)rowbase * Hdim);
            #pragma unroll
            for (int i = 0; i < 4; i++)
                hs4[l_b[i] * 128 + w * 16 + l_q[i]] =
                    __ldcg(&src[l_b[i] * 128 + w * 16 + l_q[i]]);
        } else {
            float4 z = make_float4(0.f, 0.f, 0.f, 0.f);
            #pragma unroll
            for (int i = 0; i < 4; i++)
                hs4[l_b[i] * 128 + w * 16 + l_q[i]] = z;
        }
        __syncthreads();

        float acc[8];
        #pragma unroll
        for (int b = 0; b < 8; b++) acc[b] = 0.f;
        #pragma unroll
        for (int i = 0; i < 16; i++) {
            float4 w4 = wv[i];
            #pragma unroll
            for (int b = 0; b < 8; b++) {
                float4 h4 = hs4[b * 128 + w * 16 + i];   // warp-uniform -> broadcast
                acc[b] = fmaf(h4.w, w4.w,
                          fmaf(h4.z, w4.z,
                           fmaf(h4.y, w4.y,
                            fmaf(h4.x, w4.x, acc[b]))));
            }
        }
        #pragma unroll
        for (int b = 0; b < 8; b++)
            part[(w * 8 + b) * 32 + lane] = acc[b];
        __syncthreads();

        {
            float s2 = 0.f;
            #pragma unroll
            for (int ww = 0; ww < 8; ww++)
                s2 += part[(ww * 8 + b2) * 32 + j2];
            float v = xv + s2;
            g_h[off] = fmaxf(v, 0.f);
        }
        __syncthreads();
        if (tid == 0) st_release_gpu(myflag, t + 1);
    }
}

// ---------------------------------------------------------------------------
// FC + sigmoid: out[b*T + t] = sigmoid(dot(h1[t][b], W_fc) + b_fc)
// ---------------------------------------------------------------------------
__global__ __launch_bounds__(256) void fc_sigmoid(
    const float* __restrict__ wfc, const float* __restrict__ bfc,
    float* __restrict__ out)
{
    int gw   = (blockIdx.x * blockDim.x + threadIdx.x) >> 5;  // 0..32767
    int lane = threadIdx.x & 31;
    int t = gw >> 6, b = gw & 63;

    const float4* hp = reinterpret_cast<const float4*>(g_h + (size_t)gw * Hdim);
    const float4* wp = reinterpret_cast<const float4*>(wfc);
    float s = 0.f;
    #pragma unroll
    for (int r = 0; r < 4; r++) {
        float4 hv = hp[lane + r * 32];
        float4 wv = wp[lane + r * 32];
        s += hv.x * wv.x + hv.y * wv.y + hv.z * wv.z + hv.w * wv.w;
    }
    #pragma unroll
    for (int o = 16; o > 0; o >>= 1)
        s += __shfl_xor_sync(0xffffffffu, s, o);
    if (lane == 0) {
        float v = s + bfc[0];
        out[(size_t)b * Tdim + t] = 1.f / (1.f + expf(-v));
    }
}

// ---------------------------------------------------------------------------
extern "C" void kernel_launch(void* const* d_in, const int* in_sizes, int n_in,
                              void* d_out, int out_size)
{
    (void)in_sizes; (void)n_in; (void)out_size;
    const float* x    = (const float*)d_in[0];
    const float* Wih0 = (const float*)d_in[1];
    const float* Whh0 = (const float*)d_in[2];
    const float* bih0 = (const float*)d_in[3];
    const float* bhh0 = (const float*)d_in[4];
    const float* Wih1 = (const float*)d_in[5];
    const float* Whh1 = (const float*)d_in[6];
    const float* bih1 = (const float*)d_in[7];
    const float* bhh1 = (const float*)d_in[8];
    const float* Wfc  = (const float*)d_in[9];
    const float* bfc  = (const float*)d_in[10];
    float* out = (float*)d_out;

    const int dyn_smem = TOT_FL * sizeof(float);  // 61440 B
    static bool attr_set = false;
    if (!attr_set) {
        cudaFuncSetAttribute(proj_tc<Idim, true>,
                             cudaFuncAttributeMaxDynamicSharedMemorySize, dyn_smem);
        cudaFuncSetAttribute(proj_tc<Hdim, false>,
                             cudaFuncAttributeMaxDynamicSharedMemorySize, dyn_smem);
        attr_set = true;
    }

    dim3 gemm_grid(8, 256);   // N/64, M/128
    dim3 scan_grid(16, 8);    // j-blocks, b-blocks

    zero_flags_k<<<1, 512>>>();

    // Layer 0
    proj_tc<Idim, true><<<gemm_grid, 256, dyn_smem>>>(x, Wih0, bih0, bhh0);
    rnn_scan<<<scan_grid, 256>>>(Whh0, 0);

    // Layer 1
    proj_tc<Hdim, false><<<gemm_grid, 256, dyn_smem>>>(x, Wih1, bih1, bhh1);
    rnn_scan<<<scan_grid, 256>>>(Whh1, 1);

    // Head
    fc_sigmoid<<<4096, 256>>>(Wfc, bfc, out);
}

// round 8
// speedup vs baseline: 1.9299x; 1.9299x over previous
#include <cuda_runtime.h>
#include <math.h>
#include <stdint.h>
#include <mma.h>

using namespace nvcuda;

#define Bdim 64
#define Tdim 512
#define Idim 256
#define Hdim 512
#define BH   (Bdim*Hdim)   // 32768

// Scratch (device globals: no allocations allowed)
__device__ float g_xw[(size_t)Tdim*Bdim*Hdim];  // 64 MB, [T,B,H] rows m=t*64+b
__device__ float g_h [(size_t)Tdim*Bdim*Hdim];  // 64 MB, [T,B,H]
__device__ int   g_flag[2][8][32][32];          // flags padded: one 128B line each

__global__ void zero_flags_k() {
    int i = blockIdx.x * blockDim.x + threadIdx.x;
    if (i < 2 * 8 * 32 * 32) ((int*)g_flag)[i] = 0;
}

__device__ __forceinline__ void st_release_gpu(int* p, int v) {
    asm volatile("st.release.gpu.u32 [%0], %1;" :: "l"(p), "r"(v) : "memory");
}
__device__ __forceinline__ int ld_acquire_gpu(const int* p) {
    int v;
    asm volatile("ld.acquire.gpu.u32 %0, [%1];" : "=r"(v) : "l"(p) : "memory");
    return v;
}

// ---------------------------------------------------------------------------
// 3xTF32 tensor-core projection GEMM (near-fp32 accuracy).
// g_xw[m][n] = sum_k A[m][k] * W[n][k] + b1[n] + b2[n]
// v = hi + lo (hi = tf32-rounded); C += hi*hi + hi*lo + lo*hi.
// CTA tile: M=128, N=64, K chunked by 32. 8 warps, each 32x32 (2x2 wmma 16x16x8).
// FIRST: A = x with layout [B,T,I]  (row m=t*64+b -> offset (b*T+t)*KD)
// else : A = g_h with row-major rows m (offset m*KD)
// ---------------------------------------------------------------------------
#define LDA 40                       // 32 + 8 skew
#define A_FL (128 * LDA)
#define B_FL (64 * LDA)
#define TOT_FL (2 * (A_FL + B_FL))   // 15360 floats = 61440 B
#define LDC 72                       // 64 + 8 skew

template<int KD, bool FIRST>
__global__ __launch_bounds__(256, 2) void proj_tc(
    const float* __restrict__ xin, const float* __restrict__ W,
    const float* __restrict__ b1,  const float* __restrict__ b2)
{
    extern __shared__ float s[];     // [A_hi | A_lo | B_hi | B_lo]; reused as C
    float* As_hi = s;
    float* As_lo = s + A_FL;
    float* Bs_hi = s + 2 * A_FL;
    float* Bs_lo = s + 2 * A_FL + B_FL;
    __shared__ float biasS[64];

    const float* __restrict__ A = FIRST ? xin : g_h;
    const int tid = threadIdx.x;
    const int wid = tid >> 5;
    const int n0 = blockIdx.x * 64;
    const int m0 = blockIdx.y * 128;
    const int wm = wid & 3;
    const int wn = wid >> 2;

    if (tid < 64) biasS[tid] = b1[n0 + tid] + b2[n0 + tid];

    int a_row[4], a_col[4];
    #pragma unroll
    for (int i = 0; i < 4; i++) {
        int idx = tid + i * 256;
        a_row[i] = idx >> 3;
        a_col[i] = (idx & 7) * 4;
    }
    int b_row[2], b_col[2];
    #pragma unroll
    for (int i = 0; i < 2; i++) {
        int idx = tid + i * 256;
        b_row[i] = idx >> 3;
        b_col[i] = (idx & 7) * 4;
    }

    size_t a_off[4];
    #pragma unroll
    for (int i = 0; i < 4; i++) {
        int m = m0 + a_row[i];
        a_off[i] = FIRST ? ((size_t)(m & 63) * Tdim + (m >> 6)) * KD
                         : (size_t)m * KD;
    }
    size_t b_off[2];
    #pragma unroll
    for (int i = 0; i < 2; i++)
        b_off[i] = (size_t)(n0 + b_row[i]) * KD;

    wmma::fragment<wmma::accumulator, 16, 16, 8, float> cf[2][2];
    #pragma unroll
    for (int i = 0; i < 2; i++)
        #pragma unroll
        for (int j = 0; j < 2; j++)
            wmma::fill_fragment(cf[i][j], 0.0f);

    float4 pa[4], pb[2];
    #pragma unroll
    for (int i = 0; i < 4; i++)
        pa[i] = *reinterpret_cast<const float4*>(A + a_off[i] + a_col[i]);
    #pragma unroll
    for (int i = 0; i < 2; i++)
        pb[i] = *reinterpret_cast<const float4*>(W + b_off[i] + b_col[i]);

    const int KT = KD / 32;
    for (int kt = 0; kt < KT; ++kt) {
        #pragma unroll
        for (int i = 0; i < 4; i++) {
            int o = a_row[i] * LDA + a_col[i];
            float hx = wmma::__float_to_tf32(pa[i].x);
            float hy = wmma::__float_to_tf32(pa[i].y);
            float hz = wmma::__float_to_tf32(pa[i].z);
            float hw = wmma::__float_to_tf32(pa[i].w);
            As_hi[o+0] = hx; As_hi[o+1] = hy; As_hi[o+2] = hz; As_hi[o+3] = hw;
            As_lo[o+0] = pa[i].x - hx; As_lo[o+1] = pa[i].y - hy;
            As_lo[o+2] = pa[i].z - hz; As_lo[o+3] = pa[i].w - hw;
        }
        #pragma unroll
        for (int i = 0; i < 2; i++) {
            int o = b_row[i] * LDA + b_col[i];
            float hx = wmma::__float_to_tf32(pb[i].x);
            float hy = wmma::__float_to_tf32(pb[i].y);
            float hz = wmma::__float_to_tf32(pb[i].z);
            float hw = wmma::__float_to_tf32(pb[i].w);
            Bs_hi[o+0] = hx; Bs_hi[o+1] = hy; Bs_hi[o+2] = hz; Bs_hi[o+3] = hw;
            Bs_lo[o+0] = pb[i].x - hx; Bs_lo[o+1] = pb[i].y - hy;
            Bs_lo[o+2] = pb[i].z - hz; Bs_lo[o+3] = pb[i].w - hw;
        }
        __syncthreads();

        if (kt + 1 < KT) {
            int k0 = (kt + 1) * 32;
            #pragma unroll
            for (int i = 0; i < 4; i++)
                pa[i] = *reinterpret_cast<const float4*>(A + a_off[i] + k0 + a_col[i]);
            #pragma unroll
            for (int i = 0; i < 2; i++)
                pb[i] = *reinterpret_cast<const float4*>(W + b_off[i] + k0 + b_col[i]);
        }

        #pragma unroll
        for (int kk = 0; kk < 32; kk += 8) {
            wmma::fragment<wmma::matrix_a, 16, 16, 8, wmma::precision::tf32, wmma::row_major> ah[2], al[2];
            wmma::fragment<wmma::matrix_b, 16, 16, 8, wmma::precision::tf32, wmma::col_major> bh[2], bl[2];
            #pragma unroll
            for (int i = 0; i < 2; i++) {
                wmma::load_matrix_sync(ah[i], As_hi + (wm * 32 + i * 16) * LDA + kk, LDA);
                wmma::load_matrix_sync(al[i], As_lo + (wm * 32 + i * 16) * LDA + kk, LDA);
            }
            #pragma unroll
            for (int j = 0; j < 2; j++) {
                wmma::load_matrix_sync(bh[j], Bs_hi + (wn * 32 + j * 16) * LDA + kk, LDA);
                wmma::load_matrix_sync(bl[j], Bs_lo + (wn * 32 + j * 16) * LDA + kk, LDA);
            }
            #pragma unroll
            for (int i = 0; i < 2; i++)
                #pragma unroll
                for (int j = 0; j < 2; j++) {
                    wmma::mma_sync(cf[i][j], al[i], bh[j], cf[i][j]);
                    wmma::mma_sync(cf[i][j], ah[i], bl[j], cf[i][j]);
                    wmma::mma_sync(cf[i][j], ah[i], bh[j], cf[i][j]);
                }
        }
        __syncthreads();
    }

    #pragma unroll
    for (int i = 0; i < 2; i++)
        #pragma unroll
        for (int j = 0; j < 2; j++)
            wmma::store_matrix_sync(s + (wm * 32 + i * 16) * LDC + wn * 32 + j * 16,
                                    cf[i][j], LDC, wmma::mem_row_major);
    __syncthreads();

    #pragma unroll
    for (int i = 0; i < 8; i++) {
        int idx = tid + i * 256;
        int row = idx >> 4;
        int col = (idx & 15) * 4;
        float4 o;
        o.x = s[row * LDC + col + 0] + biasS[col + 0];
        o.y = s[row * LDC + col + 1] + biasS[col + 1];
        o.z = s[row * LDC + col + 2] + biasS[col + 2];
        o.w = s[row * LDC + col + 3] + biasS[col + 3];
        *reinterpret_cast<float4*>(&g_xw[(size_t)(m0 + row) * Hdim + n0 + col]) = o;
    }
}

// ---------------------------------------------------------------------------
// Recurrent scan: h[t] = relu(xw[t] + h[t-1] @ Whh^T), persistent kernel.
// Grid (16 j-blocks, 8 b-blocks) = 128 CTAs, 256 threads each.
// W slice in registers. Per-warp pipeline: warp w consumes k-chunk
// [w*64,(w+1)*64) produced by jblks {2w, 2w+1}. Each warp polls its own two
// flags (each flag on a private 128B line to avoid LTS contention), loads its
// own 2KB h slice, and computes its partials with only a __syncwarp -- the
// CTA barrier is needed only at the cross-warp reduce.
// ---------------------------------------------------------------------------
__global__ __launch_bounds__(256) void rnn_scan(const float* __restrict__ Whh, int layer)
{
    __shared__ __align__(16) float hs[8 * 512];        // h_prev slice (8 batch rows)
    __shared__ __align__(16) float part[8 * 8 * 32];   // per-warp partials

    const int tid  = threadIdx.x;
    const int w    = tid >> 5;
    const int lane = tid & 31;
    const int jblk = blockIdx.x;   // 0..15
    const int bblk = blockIdx.y;   // 0..7
    const int j = jblk * 32 + lane;
    const int rowbase = bblk * 8;
    int* myflag = &g_flag[layer][bblk][jblk][0];
    const int* pf = (lane < 2) ? &g_flag[layer][bblk][2 * w + lane][0] : nullptr;

    // Weight-stationary registers: Whh[j][w*64 .. w*64+63]
    float4 wv[16];
    const float4* Wr = reinterpret_cast<const float4*>(Whh + (size_t)j * Hdim + w * 64);
    #pragma unroll
    for (int i = 0; i < 16; i++) wv[i] = Wr[i];

    float4* hs4 = reinterpret_cast<float4*>(hs);

    const int b2 = tid >> 5, j2 = tid & 31;
    const size_t outbase = (size_t)(rowbase + b2) * Hdim + jblk * 32 + j2;

    // Per-warp h-load slots: warp w covers float4 cols [w*16, w*16+16) of each row
    int l_b[4], l_q[4];
    #pragma unroll
    for (int i = 0; i < 4; i++) {
        int idx = lane + i * 32;      // 0..127
        l_b[i] = idx >> 4;            // row 0..7
        l_q[i] = idx & 15;            // float4 col within warp chunk
    }

    for (int t = 0; t < Tdim; ++t) {
        // Prefetch xw for this thread's output slot (independent of h[t-1])
        const size_t off = (size_t)t * BH + outbase;
        float xv = __ldcg(&g_xw[off]);

        if (t > 0) {
            // Warp w waits only on its two producers (jblk 2w, 2w+1)
            for (;;) {
                int v = (lane < 2) ? ld_acquire_gpu(pf) : 0x7fffffff;
                if (__all_sync(0xffffffffu, v >= t)) break;
            }
            const float4* src = reinterpret_cast<const float4*>(
                g_h + (size_t)(t - 1) * BH + (size_t)rowbase * Hdim);
            #pragma unroll
            for (int i = 0; i < 4; i++)
                hs4[l_b[i] * 128 + w * 16 + l_q[i]] =
                    __ldcg(&src[l_b[i] * 128 + w * 16 + l_q[i]]);
        } else {
            float4 z = make_float4(0.f, 0.f, 0.f, 0.f);
            #pragma unroll
            for (int i = 0; i < 4; i++)
                hs4[l_b[i] * 128 + w * 16 + l_q[i]] = z;
        }
        __syncwarp();   // warp w reads only its own hs slice

        float acc[8];
        #pragma unroll
        for (int b = 0; b < 8; b++) acc[b] = 0.f;
        #pragma unroll
        for (int i = 0; i < 16; i++) {
            float4 w4 = wv[i];
            #pragma unroll
            for (int b = 0; b < 8; b++) {
                float4 h4 = hs4[b * 128 + w * 16 + i];   // warp-uniform -> broadcast
                acc[b] = fmaf(h4.w, w4.w,
                          fmaf(h4.z, w4.z,
                           fmaf(h4.y, w4.y,
                            fmaf(h4.x, w4.x, acc[b]))));
            }
        }
        #pragma unroll
        for (int b = 0; b < 8; b++)
            part[(w * 8 + b) * 32 + lane] = acc[b];
        __syncthreads();

        {
            float s2 = 0.f;
            #pragma unroll
            for (int ww = 0; ww < 8; ww++)
                s2 += part[(ww * 8 + b2) * 32 + j2];
            float v = xv + s2;
            g_h[off] = fmaxf(v, 0.f);
        }
        __syncthreads();
        if (tid == 0) st_release_gpu(myflag, t + 1);
    }
}

// ---------------------------------------------------------------------------
// FC + sigmoid: out[b*T + t] = sigmoid(dot(h1[t][b], W_fc) + b_fc)
// ---------------------------------------------------------------------------
__global__ __launch_bounds__(256) void fc_sigmoid(
    const float* __restrict__ wfc, const float* __restrict__ bfc,
    float* __restrict__ out)
{
    int gw   = (blockIdx.x * blockDim.x + threadIdx.x) >> 5;  // 0..32767
    int lane = threadIdx.x & 31;
    int t = gw >> 6, b = gw & 63;

    const float4* hp = reinterpret_cast<const float4*>(g_h + (size_t)gw * Hdim);
    const float4* wp = reinterpret_cast<const float4*>(wfc);
    float s = 0.f;
    #pragma unroll
    for (int r = 0; r < 4; r++) {
        float4 hv = hp[lane + r * 32];
        float4 wv = wp[lane + r * 32];
        s += hv.x * wv.x + hv.y * wv.y + hv.z * wv.z + hv.w * wv.w;
    }
    #pragma unroll
    for (int o = 16; o > 0; o >>= 1)
        s += __shfl_xor_sync(0xffffffffu, s, o);
    if (lane == 0) {
        float v = s + bfc[0];
        out[(size_t)b * Tdim + t] = 1.f / (1.f + expf(-v));
    }
}

// ---------------------------------------------------------------------------
extern "C" void kernel_launch(void* const* d_in, const int* in_sizes, int n_in,
                              void* d_out, int out_size)
{
    (void)in_sizes; (void)n_in; (void)out_size;
    const float* x    = (const float*)d_in[0];
    const float* Wih0 = (const float*)d_in[1];
    const float* Whh0 = (const float*)d_in[2];
    const float* bih0 = (const float*)d_in[3];
    const float* bhh0 = (const float*)d_in[4];
    const float* Wih1 = (const float*)d_in[5];
    const float* Whh1 = (const float*)d_in[6];
    const float* bih1 = (const float*)d_in[7];
    const float* bhh1 = (const float*)d_in[8];
    const float* Wfc  = (const float*)d_in[9];
    const float* bfc  = (const float*)d_in[10];
    float* out = (float*)d_out;

    const int dyn_smem = TOT_FL * sizeof(float);  // 61440 B
    static bool attr_set = false;
    if (!attr_set) {
        cudaFuncSetAttribute(proj_tc<Idim, true>,
                             cudaFuncAttributeMaxDynamicSharedMemorySize, dyn_smem);
        cudaFuncSetAttribute(proj_tc<Hdim, false>,
                             cudaFuncAttributeMaxDynamicSharedMemorySize, dyn_smem);
        attr_set = true;
    }

    dim3 gemm_grid(8, 256);   // N/64, M/128
    dim3 scan_grid(16, 8);    // j-blocks, b-blocks

    zero_flags_k<<<32, 512>>>();

    // Layer 0
    proj_tc<Idim, true><<<gemm_grid, 256, dyn_smem>>>(x, Wih0, bih0, bhh0);
    rnn_scan<<<scan_grid, 256>>>(Whh0, 0);

    // Layer 1
    proj_tc<Hdim, false><<<gemm_grid, 256, dyn_smem>>>(x, Wih1, bih1, bhh1);
    rnn_scan<<<scan_grid, 256>>>(Whh1, 1);

    // Head
    fc_sigmoid<<<4096, 256>>>(Wfc, bfc, out);
}